// round 13
// baseline (speedup 1.0000x reference)
#include <cuda_runtime.h>
#include <cuda_fp16.h>
#include <cstdint>

#define D    128
#define C    21
#define HROW 32       // fp16 P-table row stride (halves) = 64B
#define MAXN 50000
#define NPT  8        // nodes per warp
#define CP   132      // padded weight row stride (floats)
#define TPB  1024     // prep threads per block
#define NPB  256      // nodes per prep block (32 warps x 8)

typedef unsigned long long ull;

// Scratch (static device globals — no allocation allowed)
__device__ __half g_PsH[MAXN * HROW];   // fp16 tables: 64B rows
__device__ __half g_PdH[MAXN * HROW];
__device__ int    g_is64;

// ---- packed fp32x2 FMA (sm_103a; PTX-only form) ----------------------------
__device__ __forceinline__ ull fma2(ull a, ull b, ull c) {
    ull d;
    asm("fma.rn.f32x2 %0, %1, %2, %3;" : "=l"(d) : "l"(a), "l"(b), "l"(c));
    return d;
}
__device__ __forceinline__ float f2sum(ull v) {
    uint32_t l, h;
    asm("mov.b64 {%0, %1}, %2;" : "=r"(l), "=r"(h) : "l"(v));
    return __uint_as_float(l) + __uint_as_float(h);
}

// ---------------------------------------------------------------------------
// prep_kernel: fused combine + nodeproj. 196 blocks x 1024 threads.
// Phase 1: every block computes Ms = Wsrc@Wcls, Md = Wdst@Wcls, bc directly
//          into ITS OWN smem (redundant across blocks — cheaper than a
//          separate latency-bound kernel + launch gap). Block 0 also runs
//          the int64/int32 detection.
// Phase 2: per-node projection for the block's 256 nodes; fp32 f32x2 FMAs;
//          stores fp16 table rows.
// ---------------------------------------------------------------------------
__global__ void __launch_bounds__(TPB) prep_kernel(const float* __restrict__ emb,
                                                   const float* __restrict__ Wsrc,
                                                   const float* __restrict__ Wdst,
                                                   const float* __restrict__ Wcls,
                                                   const float* __restrict__ bfuse,
                                                   const float* __restrict__ bcls,
                                                   const uint32_t* __restrict__ ew,
                                                   int N) {
    __shared__ float sWc[D * C];                 // 10.5 KB (phase 1 input)
    __shared__ __align__(16) float sWs[C * CP];  // 11.1 KB
    __shared__ __align__(16) float sWd[C * CP];  // 11.1 KB
    __shared__ float sbc[C];

    // dtype detection (block 0, warp 0) — independent of the rest
    if (blockIdx.x == 0 && threadIdx.x < 32) {
        int lane = threadIdx.x;
        uint32_t v = 0;
#pragma unroll
        for (int i = 0; i < 8; i++)
            v |= ew[1 + 2 * (lane + 32 * i)];   // odd words: int64 high halves
#pragma unroll
        for (int o = 16; o; o >>= 1)
            v |= __shfl_xor_sync(0xffffffffu, v, o);
        if (lane == 0) g_is64 = (v == 0u) ? 1 : 0;
    }

    // ---- Phase 1: fold weights into smem ----
    for (int i = threadIdx.x; i < D * C; i += TPB)
        sWc[i] = __ldg(&Wcls[i]);
    __syncthreads();

    for (int t = threadIdx.x; t < 2 * D * C + C; t += TPB) {
        if (t < 2 * D * C) {
            int m = t / (D * C);
            int r = t % (D * C);
            int k = r / C;
            int c = r % C;
            const float4* W4 = (const float4*)((m ? Wdst : Wsrc) + (size_t)k * D);
            float acc = 0.f;
#pragma unroll 8
            for (int j = 0; j < D / 4; j++) {
                float4 w = __ldg(W4 + j);
                acc = fmaf(w.x, sWc[(4 * j + 0) * C + c], acc);
                acc = fmaf(w.y, sWc[(4 * j + 1) * C + c], acc);
                acc = fmaf(w.z, sWc[(4 * j + 2) * C + c], acc);
                acc = fmaf(w.w, sWc[(4 * j + 3) * C + c], acc);
            }
            (m ? sWd : sWs)[c * CP + k] = acc;
        } else {
            int c = t - 2 * D * C;
            float acc = __ldg(&bcls[c]);
#pragma unroll 4
            for (int j = 0; j < D; j++)
                acc = fmaf(__ldg(&bfuse[j]), sWc[j * C + c], acc);
            sbc[c] = acc;
        }
    }
    __syncthreads();

    // ---- Phase 2: per-node projection (warp = 8 nodes x lane=class) ----
    int wid  = threadIdx.x >> 5;                 // 0..31
    int lane = threadIdx.x & 31;
    int n0   = blockIdx.x * NPB + wid * NPT;
    if (n0 >= N) return;

    int cc = (lane < C) ? lane : (C - 1);
    const ulonglong2* ws2 = (const ulonglong2*)(sWs + cc * CP);
    const ulonglong2* wd2 = (const ulonglong2*)(sWd + cc * CP);
    const ulonglong2* e2  = (const ulonglong2*)(emb + (size_t)n0 * D);

    ull as2[NPT], ad2[NPT];
#pragma unroll
    for (int j = 0; j < NPT; j++) { as2[j] = 0ull; ad2[j] = 0ull; }

    int nv = N - n0; if (nv > NPT) nv = NPT;

    if (nv == NPT) {
#pragma unroll
        for (int k = 0; k < D / 4; k++) {
            ulonglong2 ws = ws2[k];
            ulonglong2 wd = wd2[k];
#pragma unroll
            for (int j = 0; j < NPT; j++) {
                ulonglong2 ev = __ldg(e2 + (size_t)j * (D / 4) + k);  // warp broadcast
                as2[j] = fma2(ev.x, ws.x, as2[j]);
                as2[j] = fma2(ev.y, ws.y, as2[j]);
                ad2[j] = fma2(ev.x, wd.x, ad2[j]);
                ad2[j] = fma2(ev.y, wd.y, ad2[j]);
            }
        }
    } else {
        for (int k = 0; k < D / 4; k++) {
            ulonglong2 ws = ws2[k];
            ulonglong2 wd = wd2[k];
            for (int j = 0; j < nv; j++) {
                ulonglong2 ev = __ldg(e2 + (size_t)j * (D / 4) + k);
                as2[j] = fma2(ev.x, ws.x, as2[j]);
                as2[j] = fma2(ev.y, ws.y, as2[j]);
                ad2[j] = fma2(ev.x, wd.x, ad2[j]);
                ad2[j] = fma2(ev.y, wd.y, ad2[j]);
            }
        }
    }

    if (lane < C) {
        float bc = sbc[lane];
#pragma unroll
        for (int j = 0; j < NPT; j++) {
            if (j < nv) {
                size_t row = (size_t)(n0 + j) * HROW;
                g_PsH[row + lane] = __float2half_rn(f2sum(as2[j]) + bc);
                g_PdH[row + lane] = __float2half_rn(f2sum(ad2[j]));
            }
        }
    }
}

// ---------------------------------------------------------------------------
// Edge kernel: R12 form (measured best). Half-warp per edge, fp16 tables.
//  - one coalesced 32-edge index load per warp (evict-first: streamed once)
//  - lane q loads one uint32 = 2 halves of each 64B table row (unpredicated)
//  - fp16x2 -> float2 convert, fp32 add, predicated evict-first STG.32.
// ---------------------------------------------------------------------------
__global__ void __launch_bounds__(256) edge_kernel(const uint32_t* __restrict__ ew,
                                                   float* __restrict__ out,
                                                   uint32_t E) {
    const uint32_t F = 0xffffffffu;
    uint32_t wid  = threadIdx.x >> 5;
    uint32_t lane = threadIdx.x & 31;
    uint32_t warp = blockIdx.x * 8u + wid;
    uint32_t e0   = warp * 32u;
    if (e0 >= E) return;

    uint32_t myE = e0 + lane;
    bool have = (myE < E);
    uint32_t sv = 0, dv = 0;
    if (g_is64) {
        const uint2* ew2 = (const uint2*)ew;
        if (have) {
            sv = __ldcs(&ew2[myE]).x;
            dv = __ldcs(&ew2[(size_t)E + myE]).x;
        }
    } else {
        if (have) {
            sv = __ldcs(&ew[myE]);
            dv = __ldcs(&ew[(size_t)E + myE]);
        }
    }

    const uint32_t* __restrict__ PsU = (const uint32_t*)g_PsH;  // row = 16 uints (64B)
    const uint32_t* __restrict__ PdU = (const uint32_t*)g_PdH;

    uint32_t h = lane >> 4;          // half id: edge parity within the pair
    uint32_t q = lane & 15;          // half2 index within row
    uint32_t nIt = E - e0; if (nIt > 32u) nIt = 32u;

    if (nIt == 32u) {
#pragma unroll 8
        for (int it = 0; it < 16; ++it) {
            uint32_t eidx = 2u * (uint32_t)it + h;
            uint32_t s = __shfl_sync(F, sv, eidx);
            uint32_t d = __shfl_sync(F, dv, eidx);
            uint32_t a = __ldg(PsU + (size_t)s * 16u + q);   // in-row for all q
            uint32_t b = __ldg(PdU + (size_t)d * 16u + q);
            float2 fa = __half22float2(*(__half2*)&a);
            float2 fb = __half22float2(*(__half2*)&b);
            float lo = fa.x + fb.x;
            float hi = fa.y + fb.y;
            float* base = out + (size_t)(e0 + eidx) * C;
            if (q <= 10u) __stcs(base + 2u * q, lo);        // floats 0,2,...,20
            if (q <= 9u)  __stcs(base + 2u * q + 1u, hi);   // floats 1,3,...,19
        }
    } else {
        for (uint32_t it = 0; it < nIt; ++it) {
            uint32_t s = __shfl_sync(F, sv, it);
            uint32_t d = __shfl_sync(F, dv, it);
            if (lane < C) {
                float v = __half2float(g_PsH[(size_t)s * HROW + lane]) +
                          __half2float(g_PdH[(size_t)d * HROW + lane]);
                out[(size_t)(e0 + it) * C + lane] = v;
            }
        }
    }
}

// ---------------------------------------------------------------------------
extern "C" void kernel_launch(void* const* d_in, const int* in_sizes, int n_in,
                              void* d_out, int out_size) {
    const float*    emb   = (const float*)d_in[0];
    const uint32_t* ei    = (const uint32_t*)d_in[1];
    const float*    Wsrc  = (const float*)d_in[2];
    const float*    Wdst  = (const float*)d_in[3];
    const float*    bfuse = (const float*)d_in[4];
    const float*    Wcls  = (const float*)d_in[5];
    const float*    bcls  = (const float*)d_in[6];
    float* out = (float*)d_out;

    int N = in_sizes[0] / D;          // 50000
    int E = in_sizes[1] / 2;          // 1600000

    int pblocks = (N + NPB - 1) / NPB;   // 196
    prep_kernel<<<pblocks, TPB>>>(emb, Wsrc, Wdst, Wcls, bfuse, bcls, ei, N);

    uint32_t warps  = ((uint32_t)E + 31u) / 32u;
    uint32_t blocks = (warps + 7u) / 8u;
    edge_kernel<<<blocks, 256>>>(ei, out, (uint32_t)E);
}

// round 14
// speedup vs baseline: 1.8676x; 1.8676x over previous
#include <cuda_runtime.h>
#include <cuda_fp16.h>
#include <cstdint>

#define D    128
#define C    21
#define HROW 32       // fp16 P-table row stride (halves) = 64B
#define MAXN 50000
#define NPT  8        // nodes per warp in nodeproj
#define CP   132

typedef unsigned long long ull;

// Scratch (static device globals — no allocation allowed)
__device__ float  g_WsT[C * CP];
__device__ float  g_WdT[C * CP];
__device__ float  g_bc[C];
__device__ __half g_PsH[MAXN * HROW];   // fp16 tables: 64B rows, 2 sectors/gather
__device__ __half g_PdH[MAXN * HROW];
__device__ int    g_is64;

// ---- packed fp32x2 FMA (sm_103a; PTX-only form) ----------------------------
__device__ __forceinline__ ull fma2(ull a, ull b, ull c) {
    ull d;
    asm("fma.rn.f32x2 %0, %1, %2, %3;" : "=l"(d) : "l"(a), "l"(b), "l"(c));
    return d;
}
__device__ __forceinline__ float f2sum(ull v) {
    uint32_t l, h;
    asm("mov.b64 {%0, %1}, %2;" : "=r"(l), "=r"(h) : "l"(v));
    return __uint_as_float(l) + __uint_as_float(h);
}

// ---------------------------------------------------------------------------
// combine_kernel (R12 form; runs ONCE — the R13 per-block refold was a 527MB
// traffic mistake). 8 lanes per output, shfl-tree reduce, no smem/sync.
// Last block: dtype detection + PARALLEL bias fold (4 lanes per class).
// ---------------------------------------------------------------------------
__global__ void __launch_bounds__(256) combine_kernel(const float* __restrict__ Wsrc,
                                                      const float* __restrict__ Wdst,
                                                      const float* __restrict__ Wcls,
                                                      const float* __restrict__ bfuse,
                                                      const float* __restrict__ bcls,
                                                      const uint32_t* __restrict__ ew) {
    if (blockIdx.x == gridDim.x - 1) {
        if (threadIdx.x < 32) {
            int lane = threadIdx.x;
            uint32_t v = 0;
#pragma unroll
            for (int i = 0; i < 8; i++)
                v |= ew[1 + 2 * (lane + 32 * i)];   // odd words: int64 high halves
#pragma unroll
            for (int o = 16; o; o >>= 1)
                v |= __shfl_xor_sync(0xffffffffu, v, o);
            if (lane == 0) g_is64 = (v == 0u) ? 1 : 0;
        } else if (threadIdx.x >= 64 && threadIdx.x < 64 + 4 * C) {
            // bias fold, 4 lanes per class: bc = b_fuse @ Wcls + b_cls
            int t = threadIdx.x - 64;
            int c = t >> 2;
            int p = t & 3;                    // quarter of K (32 elems)
            float acc = 0.f;
#pragma unroll 8
            for (int j = 0; j < 32; j++) {
                int e = 32 * p + j;
                acc = fmaf(__ldg(&bfuse[e]), __ldg(&Wcls[e * C + c]), acc);
            }
            acc += __shfl_down_sync(0xffffffffu, acc, 1);
            acc += __shfl_down_sync(0xffffffffu, acc, 2);
            if (p == 0) g_bc[c] = acc + __ldg(&bcls[c]);
        }
        return;
    }

    int t = blockIdx.x * blockDim.x + threadIdx.x;
    int o = t >> 3;                                  // output id in [0, 2*D*C)
    int p = t & 7;                                   // eighth of K (16 elems)
    int m = o / (D * C);
    int r = o % (D * C);
    int k = r / C;
    int c = r % C;

    const float4* W4 = (const float4*)((m ? Wdst : Wsrc) + (size_t)k * D) + 4 * p;
    float acc = 0.f;
#pragma unroll
    for (int j = 0; j < 4; j++) {
        float4 w = __ldg(W4 + j);
        int e = 16 * p + 4 * j;
        acc = fmaf(w.x, __ldg(&Wcls[(e + 0) * C + c]), acc);
        acc = fmaf(w.y, __ldg(&Wcls[(e + 1) * C + c]), acc);
        acc = fmaf(w.z, __ldg(&Wcls[(e + 2) * C + c]), acc);
        acc = fmaf(w.w, __ldg(&Wcls[(e + 3) * C + c]), acc);
    }
    acc += __shfl_down_sync(0xffffffffu, acc, 4);
    acc += __shfl_down_sync(0xffffffffu, acc, 2);
    acc += __shfl_down_sync(0xffffffffu, acc, 1);
    if (p == 0)
        (m ? g_WdT : g_WsT)[c * CP + k] = acc;
}

// ---------------------------------------------------------------------------
// Per-node projection (R12 form): warp = NPT nodes x (lane = class), f32x2
// FMAs; fp32 accumulate, fp16 table stores.
// ---------------------------------------------------------------------------
__global__ void __launch_bounds__(256) nodeproj_kernel(const float* __restrict__ emb, int N) {
    __shared__ __align__(16) float sWs[C * CP];
    __shared__ __align__(16) float sWd[C * CP];
    __shared__ float sbc[C];
    for (int i = threadIdx.x; i < C * CP; i += blockDim.x) {
        sWs[i] = g_WsT[i];
        sWd[i] = g_WdT[i];
    }
    if (threadIdx.x < C) sbc[threadIdx.x] = g_bc[threadIdx.x];
    __syncthreads();

    int wid  = threadIdx.x >> 5;
    int lane = threadIdx.x & 31;
    int n0   = (blockIdx.x * 8 + wid) * NPT;
    if (n0 >= N) return;

    int cc = (lane < C) ? lane : (C - 1);
    const ulonglong2* ws2 = (const ulonglong2*)(sWs + cc * CP);
    const ulonglong2* wd2 = (const ulonglong2*)(sWd + cc * CP);
    const ulonglong2* e2  = (const ulonglong2*)(emb + (size_t)n0 * D);

    ull as2[NPT], ad2[NPT];
#pragma unroll
    for (int j = 0; j < NPT; j++) { as2[j] = 0ull; ad2[j] = 0ull; }

    int nv = N - n0; if (nv > NPT) nv = NPT;

    if (nv == NPT) {
#pragma unroll
        for (int k = 0; k < D / 4; k++) {
            ulonglong2 ws = ws2[k];
            ulonglong2 wd = wd2[k];
#pragma unroll
            for (int j = 0; j < NPT; j++) {
                ulonglong2 ev = __ldg(e2 + (size_t)j * (D / 4) + k);  // warp broadcast
                as2[j] = fma2(ev.x, ws.x, as2[j]);
                as2[j] = fma2(ev.y, ws.y, as2[j]);
                ad2[j] = fma2(ev.x, wd.x, ad2[j]);
                ad2[j] = fma2(ev.y, wd.y, ad2[j]);
            }
        }
    } else {
        for (int k = 0; k < D / 4; k++) {
            ulonglong2 ws = ws2[k];
            ulonglong2 wd = wd2[k];
            for (int j = 0; j < nv; j++) {
                ulonglong2 ev = __ldg(e2 + (size_t)j * (D / 4) + k);
                as2[j] = fma2(ev.x, ws.x, as2[j]);
                as2[j] = fma2(ev.y, ws.y, as2[j]);
                ad2[j] = fma2(ev.x, wd.x, ad2[j]);
                ad2[j] = fma2(ev.y, wd.y, ad2[j]);
            }
        }
    }

    if (lane < C) {
        float bc = sbc[lane];
#pragma unroll
        for (int j = 0; j < NPT; j++) {
            if (j < nv) {
                size_t row = (size_t)(n0 + j) * HROW;
                g_PsH[row + lane] = __float2half_rn(f2sum(as2[j]) + bc);
                g_PdH[row + lane] = __float2half_rn(f2sum(ad2[j]));
            }
        }
    }
}

// ---------------------------------------------------------------------------
// Edge kernel: exact R12 form (measured best). Half-warp per edge, fp16
// tables, __ldg index loads (the R13 __ldcs variant showed no benefit).
// ---------------------------------------------------------------------------
__global__ void __launch_bounds__(256) edge_kernel(const uint32_t* __restrict__ ew,
                                                   float* __restrict__ out,
                                                   uint32_t E) {
    const uint32_t F = 0xffffffffu;
    uint32_t wid  = threadIdx.x >> 5;
    uint32_t lane = threadIdx.x & 31;
    uint32_t warp = blockIdx.x * 8u + wid;
    uint32_t e0   = warp * 32u;
    if (e0 >= E) return;

    uint32_t myE = e0 + lane;
    bool have = (myE < E);
    uint32_t sv = 0, dv = 0;
    if (g_is64) {
        const uint2* ew2 = (const uint2*)ew;
        if (have) {
            sv = ew2[myE].x;
            dv = ew2[(size_t)E + myE].x;
        }
    } else {
        if (have) {
            sv = ew[myE];
            dv = ew[(size_t)E + myE];
        }
    }

    const uint32_t* __restrict__ PsU = (const uint32_t*)g_PsH;  // row = 16 uints (64B)
    const uint32_t* __restrict__ PdU = (const uint32_t*)g_PdH;

    uint32_t h = lane >> 4;          // half id: edge parity within the pair
    uint32_t q = lane & 15;          // half2 index within row
    uint32_t nIt = E - e0; if (nIt > 32u) nIt = 32u;

    if (nIt == 32u) {
#pragma unroll 8
        for (int it = 0; it < 16; ++it) {
            uint32_t eidx = 2u * (uint32_t)it + h;
            uint32_t s = __shfl_sync(F, sv, eidx);
            uint32_t d = __shfl_sync(F, dv, eidx);
            uint32_t a = __ldg(PsU + (size_t)s * 16u + q);   // in-row for all q
            uint32_t b = __ldg(PdU + (size_t)d * 16u + q);
            float2 fa = __half22float2(*(__half2*)&a);
            float2 fb = __half22float2(*(__half2*)&b);
            float lo = fa.x + fb.x;
            float hi = fa.y + fb.y;
            float* base = out + (size_t)(e0 + eidx) * C;
            if (q <= 10u) __stcs(base + 2u * q, lo);        // floats 0,2,...,20
            if (q <= 9u)  __stcs(base + 2u * q + 1u, hi);   // floats 1,3,...,19
        }
    } else {
        for (uint32_t it = 0; it < nIt; ++it) {
            uint32_t s = __shfl_sync(F, sv, it);
            uint32_t d = __shfl_sync(F, dv, it);
            if (lane < C) {
                float v = __half2float(g_PsH[(size_t)s * HROW + lane]) +
                          __half2float(g_PdH[(size_t)d * HROW + lane]);
                out[(size_t)(e0 + it) * C + lane] = v;
            }
        }
    }
}

// ---------------------------------------------------------------------------
extern "C" void kernel_launch(void* const* d_in, const int* in_sizes, int n_in,
                              void* d_out, int out_size) {
    const float*    emb   = (const float*)d_in[0];
    const uint32_t* ei    = (const uint32_t*)d_in[1];
    const float*    Wsrc  = (const float*)d_in[2];
    const float*    Wdst  = (const float*)d_in[3];
    const float*    bfuse = (const float*)d_in[4];
    const float*    Wcls  = (const float*)d_in[5];
    const float*    bcls  = (const float*)d_in[6];
    float* out = (float*)d_out;

    int N = in_sizes[0] / D;          // 50000
    int E = in_sizes[1] / 2;          // 1600000

    int cblocks = (2 * D * C * 8) / 256 + 1;   // 168 compute + 1 detect/bias
    combine_kernel<<<cblocks, 256>>>(Wsrc, Wdst, Wcls, bfuse, bcls, ei);

    int nodesPerBlock = 8 * NPT;
    nodeproj_kernel<<<(N + nodesPerBlock - 1) / nodesPerBlock, 256>>>(emb, N);

    uint32_t warps  = ((uint32_t)E + 31u) / 32u;
    uint32_t blocks = (warps + 7u) / 8u;
    edge_kernel<<<blocks, 256>>>(ei, out, (uint32_t)E);
}

// round 15
// speedup vs baseline: 1.9244x; 1.0304x over previous
#include <cuda_runtime.h>
#include <cuda_fp16.h>
#include <cstdint>

#define D    128
#define C    21
#define HROW 32       // fp16 P-table row stride (halves) = 64B
#define MAXN 50000
#define NPT  8        // nodes per warp in nodeproj
#define CP   132

typedef unsigned long long ull;

// Scratch (static device globals — no allocation allowed)
__device__ float  g_WsT[C * CP];
__device__ float  g_WdT[C * CP];
__device__ float  g_bc[C];
__device__ __half g_PsH [MAXN * HROW];  // normal rows: half i = P[i]
__device__ __half g_PdH [MAXN * HROW];
__device__ __half g_PsRH[MAXN * HROW];  // rotated:   half j = P[j+1] (j<=19), half20 = P[0]
__device__ __half g_PdRH[MAXN * HROW];
__device__ int    g_is64;

// ---- packed fp32x2 FMA (sm_103a; PTX-only form) ----------------------------
__device__ __forceinline__ ull fma2(ull a, ull b, ull c) {
    ull d;
    asm("fma.rn.f32x2 %0, %1, %2, %3;" : "=l"(d) : "l"(a), "l"(b), "l"(c));
    return d;
}
__device__ __forceinline__ float f2sum(ull v) {
    uint32_t l, h;
    asm("mov.b64 {%0, %1}, %2;" : "=r"(l), "=r"(h) : "l"(v));
    return __uint_as_float(l) + __uint_as_float(h);
}
__device__ __forceinline__ ull pack2f(float lo, float hi) {
    ull r;
    asm("mov.b64 %0, {%1, %2};" : "=l"(r)
        : "r"(__float_as_uint(lo)), "r"(__float_as_uint(hi)));
    return r;
}

// ---------------------------------------------------------------------------
// combine_kernel (R14 form, measured 6.6us). 8 lanes/output, shfl reduce.
// Last block: dtype detection + parallel bias fold.
// ---------------------------------------------------------------------------
__global__ void __launch_bounds__(256) combine_kernel(const float* __restrict__ Wsrc,
                                                      const float* __restrict__ Wdst,
                                                      const float* __restrict__ Wcls,
                                                      const float* __restrict__ bfuse,
                                                      const float* __restrict__ bcls,
                                                      const uint32_t* __restrict__ ew) {
    if (blockIdx.x == gridDim.x - 1) {
        if (threadIdx.x < 32) {
            int lane = threadIdx.x;
            uint32_t v = 0;
#pragma unroll
            for (int i = 0; i < 8; i++)
                v |= ew[1 + 2 * (lane + 32 * i)];   // odd words: int64 high halves
#pragma unroll
            for (int o = 16; o; o >>= 1)
                v |= __shfl_xor_sync(0xffffffffu, v, o);
            if (lane == 0) g_is64 = (v == 0u) ? 1 : 0;
        } else if (threadIdx.x >= 64 && threadIdx.x < 64 + 4 * C) {
            int t = threadIdx.x - 64;
            int c = t >> 2;
            int p = t & 3;
            float acc = 0.f;
#pragma unroll 8
            for (int j = 0; j < 32; j++) {
                int e = 32 * p + j;
                acc = fmaf(__ldg(&bfuse[e]), __ldg(&Wcls[e * C + c]), acc);
            }
            acc += __shfl_down_sync(0xffffffffu, acc, 1);
            acc += __shfl_down_sync(0xffffffffu, acc, 2);
            if (p == 0) g_bc[c] = acc + __ldg(&bcls[c]);
        }
        return;
    }

    int t = blockIdx.x * blockDim.x + threadIdx.x;
    int o = t >> 3;
    int p = t & 7;
    int m = o / (D * C);
    int r = o % (D * C);
    int k = r / C;
    int c = r % C;

    const float4* W4 = (const float4*)((m ? Wdst : Wsrc) + (size_t)k * D) + 4 * p;
    float acc = 0.f;
#pragma unroll
    for (int j = 0; j < 4; j++) {
        float4 w = __ldg(W4 + j);
        int e = 16 * p + 4 * j;
        acc = fmaf(w.x, __ldg(&Wcls[(e + 0) * C + c]), acc);
        acc = fmaf(w.y, __ldg(&Wcls[(e + 1) * C + c]), acc);
        acc = fmaf(w.z, __ldg(&Wcls[(e + 2) * C + c]), acc);
        acc = fmaf(w.w, __ldg(&Wcls[(e + 3) * C + c]), acc);
    }
    acc += __shfl_down_sync(0xffffffffu, acc, 4);
    acc += __shfl_down_sync(0xffffffffu, acc, 2);
    acc += __shfl_down_sync(0xffffffffu, acc, 1);
    if (p == 0)
        (m ? g_WdT : g_WsT)[c * CP + k] = acc;
}

// ---------------------------------------------------------------------------
// Per-node projection: warp = NPT nodes x (lane = class), f32x2 FMAs.
// Writes normal AND rotated fp16 rows (rotation enables the edge kernel's
// aligned single-STG.64 store path).
// ---------------------------------------------------------------------------
__global__ void __launch_bounds__(256) nodeproj_kernel(const float* __restrict__ emb, int N) {
    __shared__ __align__(16) float sWs[C * CP];
    __shared__ __align__(16) float sWd[C * CP];
    __shared__ float sbc[C];
    for (int i = threadIdx.x; i < C * CP; i += blockDim.x) {
        sWs[i] = g_WsT[i];
        sWd[i] = g_WdT[i];
    }
    if (threadIdx.x < C) sbc[threadIdx.x] = g_bc[threadIdx.x];
    __syncthreads();

    int wid  = threadIdx.x >> 5;
    int lane = threadIdx.x & 31;
    int n0   = (blockIdx.x * 8 + wid) * NPT;
    if (n0 >= N) return;

    int cc = (lane < C) ? lane : (C - 1);
    const ulonglong2* ws2 = (const ulonglong2*)(sWs + cc * CP);
    const ulonglong2* wd2 = (const ulonglong2*)(sWd + cc * CP);
    const ulonglong2* e2  = (const ulonglong2*)(emb + (size_t)n0 * D);

    ull as2[NPT], ad2[NPT];
#pragma unroll
    for (int j = 0; j < NPT; j++) { as2[j] = 0ull; ad2[j] = 0ull; }

    int nv = N - n0; if (nv > NPT) nv = NPT;

    if (nv == NPT) {
#pragma unroll
        for (int k = 0; k < D / 4; k++) {
            ulonglong2 ws = ws2[k];
            ulonglong2 wd = wd2[k];
#pragma unroll
            for (int j = 0; j < NPT; j++) {
                ulonglong2 ev = __ldg(e2 + (size_t)j * (D / 4) + k);  // warp broadcast
                as2[j] = fma2(ev.x, ws.x, as2[j]);
                as2[j] = fma2(ev.y, ws.y, as2[j]);
                ad2[j] = fma2(ev.x, wd.x, ad2[j]);
                ad2[j] = fma2(ev.y, wd.y, ad2[j]);
            }
        }
    } else {
        for (int k = 0; k < D / 4; k++) {
            ulonglong2 ws = ws2[k];
            ulonglong2 wd = wd2[k];
            for (int j = 0; j < nv; j++) {
                ulonglong2 ev = __ldg(e2 + (size_t)j * (D / 4) + k);
                as2[j] = fma2(ev.x, ws.x, as2[j]);
                as2[j] = fma2(ev.y, ws.y, as2[j]);
                ad2[j] = fma2(ev.x, wd.x, ad2[j]);
                ad2[j] = fma2(ev.y, wd.y, ad2[j]);
            }
        }
    }

    if (lane < C) {
        float bc = sbc[lane];
        int pos = (lane == 0) ? 20 : (lane - 1);   // rotated-row position of class `lane`
#pragma unroll
        for (int j = 0; j < NPT; j++) {
            if (j < nv) {
                size_t row = (size_t)(n0 + j) * HROW;
                __half vs = __float2half_rn(f2sum(as2[j]) + bc);
                __half vd = __float2half_rn(f2sum(ad2[j]));
                g_PsH [row + lane] = vs;
                g_PdH [row + lane] = vd;
                g_PsRH[row + pos]  = vs;
                g_PdRH[row + pos]  = vd;
            }
        }
    }
}

// ---------------------------------------------------------------------------
// Edge kernel: half-warp per edge (R12 gather form) + rotation-merged stores.
// Per iteration (edges A=even, B=odd):
//  - half 0 gathers A from NORMAL rows: lane q -> floats (2q, 2q+1)
//  - half 1 gathers B from ROTATED rows: lane q -> floats (2q+1, 2q+2)
//    (q=10: A -> (F20,pad); B -> (F0,pad))
//  - one shfl merges the adjacent stragglers (A.F20, B.F0) into lane 10
//  - ONE STG.64 instruction stores all 21 aligned ull slots of the 168B
//    pair-block: store wavefronts 4 -> 2 per iteration.
// ---------------------------------------------------------------------------
__global__ void __launch_bounds__(256) edge_kernel(const uint32_t* __restrict__ ew,
                                                   float* __restrict__ out,
                                                   uint32_t E) {
    const uint32_t F = 0xffffffffu;
    uint32_t wid  = threadIdx.x >> 5;
    uint32_t lane = threadIdx.x & 31;
    uint32_t warp = blockIdx.x * 8u + wid;
    uint32_t e0   = warp * 32u;
    if (e0 >= E) return;

    uint32_t myE = e0 + lane;
    bool have = (myE < E);
    uint32_t sv = 0, dv = 0;
    if (g_is64) {
        const uint2* ew2 = (const uint2*)ew;
        if (have) {
            sv = ew2[myE].x;
            dv = ew2[(size_t)E + myE].x;
        }
    } else {
        if (have) {
            sv = ew[myE];
            dv = ew[(size_t)E + myE];
        }
    }

    uint32_t h = lane >> 4;          // half id: edge parity within the pair
    uint32_t q = lane & 15;          // half2 index within row
    const uint32_t* __restrict__ PsU = h ? (const uint32_t*)g_PsRH : (const uint32_t*)g_PsH;
    const uint32_t* __restrict__ PdU = h ? (const uint32_t*)g_PdRH : (const uint32_t*)g_PdH;

    uint32_t nIt = E - e0; if (nIt > 32u) nIt = 32u;

    if (nIt == 32u) {
        // store byte offset within the 168B pair-block; pred: q<=10-h
        uint32_t soff = h ? (88u + 8u * q) : (8u * q);
        bool doStore = (q + h <= 10u);
        char* wbase = (char*)(out + (size_t)e0 * C);   // 2688B-aligned

#pragma unroll 8
        for (int it = 0; it < 16; ++it) {
            uint32_t eidx = 2u * (uint32_t)it + h;
            uint32_t s = __shfl_sync(F, sv, eidx);
            uint32_t d = __shfl_sync(F, dv, eidx);
            uint32_t a = __ldg(PsU + (size_t)s * 16u + q);
            uint32_t b = __ldg(PdU + (size_t)d * 16u + q);
            float2 fa = __half22float2(*(__half2*)&a);
            float2 fb = __half22float2(*(__half2*)&b);
            float lo = fa.x + fb.x;
            float hi = fa.y + fb.y;
            float b0 = __shfl_sync(F, lo, 26);          // B's straggler (F0)
            ull v = (lane == 10u) ? pack2f(lo, b0)      // slot10 = (A.F20, B.F0)
                                  : pack2f(lo, hi);
            if (doStore)
                __stcs((ull*)(wbase + 168u * (uint32_t)it + soff), v);
        }
    } else {
        for (uint32_t it = 0; it < nIt; ++it) {
            uint32_t s = __shfl_sync(F, sv, it);
            uint32_t d = __shfl_sync(F, dv, it);
            if (lane < C) {
                float v = __half2float(g_PsH[(size_t)s * HROW + lane]) +
                          __half2float(g_PdH[(size_t)d * HROW + lane]);
                out[(size_t)(e0 + it) * C + lane] = v;
            }
        }
    }
}

// ---------------------------------------------------------------------------
extern "C" void kernel_launch(void* const* d_in, const int* in_sizes, int n_in,
                              void* d_out, int out_size) {
    const float*    emb   = (const float*)d_in[0];
    const uint32_t* ei    = (const uint32_t*)d_in[1];
    const float*    Wsrc  = (const float*)d_in[2];
    const float*    Wdst  = (const float*)d_in[3];
    const float*    bfuse = (const float*)d_in[4];
    const float*    Wcls  = (const float*)d_in[5];
    const float*    bcls  = (const float*)d_in[6];
    float* out = (float*)d_out;

    int N = in_sizes[0] / D;          // 50000
    int E = in_sizes[1] / 2;          // 1600000

    int cblocks = (2 * D * C * 8) / 256 + 1;   // 168 compute + 1 detect/bias
    combine_kernel<<<cblocks, 256>>>(Wsrc, Wdst, Wcls, bfuse, bcls, ei);

    int nodesPerBlock = 8 * NPT;
    nodeproj_kernel<<<(N + nodesPerBlock - 1) / nodesPerBlock, 256>>>(emb, N);

    uint32_t warps  = ((uint32_t)E + 31u) / 32u;
    uint32_t blocks = (warps + 7u) / 8u;
    edge_kernel<<<blocks, 256>>>(ei, out, (uint32_t)E);
}